// round 5
// baseline (speedup 1.0000x reference)
#include <cuda_runtime.h>
#include <math.h>

#define BB    2
#define TT    5
#define CC    64
#define HH    128
#define WW    128
#define H2    64
#define W2    64
#define GG    8
#define KK9   9
#define OFFC  144      // G*2*KK = 8*2*9
#define TCEN  2        // center frame T//2
#define NJ    8        // B*(T-1) jobs
#define HW    (HH*WW)  // 16384
#define HW2   (H2*W2)  // 4096

typedef unsigned long long ull;

// packed f32x2 helpers (Blackwell sm_103a dual-lane fp32 pipe)
__device__ __forceinline__ ull ffma2(ull a, ull b, ull c) {
    ull d;
    asm("fma.rn.f32x2 %0, %1, %2, %3;" : "=l"(d) : "l"(a), "l"(b), "l"(c));
    return d;
}
__device__ __forceinline__ ull pk2(float lo, float hi) {
    ull r;
    asm("mov.b64 %0, {%1, %2};" : "=l"(r)
        : "r"(__float_as_uint(lo)), "r"(__float_as_uint(hi)));
    return r;
}
__device__ __forceinline__ void upk2(ull v, float& lo, float& hi) {
    unsigned int a, b;
    asm("mov.b64 {%0, %1}, %2;" : "=r"(a), "=r"(b) : "l"(v));
    lo = __uint_as_float(a); hi = __uint_as_float(b);
}

// ---- scratch (device globals; no allocations allowed) ----
__device__ float g_x2[BB*TT*CC*HW2];          //  downsampled frames
__device__ float g_off2[NJ*OFFC*HW2];         //  coarse offsets
__device__ float g_off2us[NJ*OFFC*HW];        //  upsampled offsets *2
__device__ float g_z1[NJ*CC*HW];              //  first deform output
__device__ float g_off1[NJ*OFFC*HW];          //  fine offsets
// deform weights repacked: [(k*8+g)*32 + o2][c] float2 = (w[2*o2][c], w[2*o2+1][c])
__device__ float2 g_wa1t2[KK9*GG*32*8];
__device__ float2 g_waft2[KK9*GG*32*8];

__device__ __forceinline__ int job_frame(int fi) { return fi + (fi >= TCEN ? 1 : 0); }

// ---------------------------------------------------------------------------
// 1) 2x2 average pool: x -> g_x2
// ---------------------------------------------------------------------------
__global__ void k_downsample(const float* __restrict__ x) {
    int idx = blockIdx.x * blockDim.x + threadIdx.x;
    if (idx >= BB*TT*CC*HW2) return;
    int xx = idx & 63;
    int yy = (idx >> 6) & 63;
    int c  = (idx >> 12) & 63;
    int bt = idx >> 18;
    const float* s = x + ((size_t)bt*CC + c)*HW + (yy*2)*WW + xx*2;
    g_x2[idx] = 0.25f * (s[0] + s[1] + s[WW] + s[WW+1]);
}

// ---------------------------------------------------------------------------
// 2) center frame passthrough
// ---------------------------------------------------------------------------
__global__ void k_center(const float* __restrict__ x, float* __restrict__ out) {
    int idx = blockIdx.x * blockDim.x + threadIdx.x;
    if (idx >= BB*CC*HW) return;
    int b    = idx >> 20;
    int rest = idx & ((1 << 20) - 1);
    size_t off = ((size_t)(b*TT + TCEN) << 20) + rest;
    out[off] = x[off];
}

// ---------------------------------------------------------------------------
// 3) repack deform weights into pair-interleaved layout:
//    dst[((k*8+g)*32 + o2)*8 + c] = (w[2*o2][g*8+c], w[2*o2+1][g*8+c])
// ---------------------------------------------------------------------------
__global__ void k_wtrans(const float* __restrict__ w1, const float* __restrict__ wf) {
    int idx = blockIdx.x * blockDim.x + threadIdx.x;
    if (idx >= KK9*GG*32*8) return;
    int c  = idx & 7;
    int o2 = (idx >> 3) & 31;
    int g  = (idx >> 8) & 7;
    int k  = idx >> 11;
    int s0 = ((2*o2    )*CC + g*8 + c)*KK9 + k;
    int s1 = ((2*o2 + 1)*CC + g*8 + c)*KK9 + k;
    g_wa1t2[idx] = make_float2(w1[s0], w1[s1]);
    g_waft2[idx] = make_float2(wf[s0], wf[s1]);
}

// ---------------------------------------------------------------------------
// 4) conv3x3 pad1 @64x64, Cin=128, Cout=144, +bias  (packed f32x2, ci chunk 4)
//    block 16x16 thr, 32x32 px tile, 2x2 px/thread (px pair packed), 16 co
// ---------------------------------------------------------------------------
#define CI3 4
__global__ __launch_bounds__(256, 2)
void k_conv3(const float* __restrict__ wg, const float* __restrict__ bias) {
    int zc  = blockIdx.z;
    int job = zc / 9, cot = zc % 9;
    int b = job >> 2, fi = job & 3;
    int frame = job_frame(fi);
    int x0 = blockIdx.x * 32, y0 = blockIdx.y * 32;
    int tx = threadIdx.x, ty = threadIdx.y;
    int tid = ty * 16 + tx;

    __shared__ float  sIn[CI3][34*34];
    __shared__ float2 sW2[CI3][16*9];

    ull acc[16][2];
    #pragma unroll
    for (int i = 0; i < 16; i++) { acc[i][0] = 0ull; acc[i][1] = 0ull; }

    const float* srcN = g_x2 + ((b*TT + frame)*CC)*HW2;
    const float* srcC = g_x2 + ((b*TT + TCEN )*CC)*HW2;

    for (int c0 = 0; c0 < 2*CC; c0 += CI3) {
        __syncthreads();
        for (int l = tid; l < CI3*34*34; l += 256) {
            int ci = l / (34*34), r = l % (34*34);
            int ly = r / 34, lx = r % 34;
            int cig = c0 + ci;
            const float* src = (cig < CC) ? (srcN + cig*HW2) : (srcC + (cig-CC)*HW2);
            int gy = y0 + ly - 1, gx = x0 + lx - 1;
            sIn[ci][r] = (gy >= 0 && gy < H2 && gx >= 0 && gx < W2) ? src[gy*W2 + gx] : 0.f;
        }
        for (int l = tid; l < CI3*144; l += 256) {
            int ci = l / 144, q = l % 144;
            int co = q / 9, k = q % 9;
            float w = wg[((cot*16 + co)*(2*CC) + c0 + ci)*9 + k];
            sW2[ci][q] = make_float2(w, w);
        }
        __syncthreads();

        int py = ty*2, px = tx*2;
        #pragma unroll
        for (int ci = 0; ci < CI3; ci++) {
            float r[4][4];
            #pragma unroll
            for (int yy = 0; yy < 4; yy++)
                #pragma unroll
                for (int xx = 0; xx < 4; xx++)
                    r[yy][xx] = sIn[ci][(py+yy)*34 + px + xx];
            ull p2[4][3];
            #pragma unroll
            for (int yy = 0; yy < 4; yy++)
                #pragma unroll
                for (int kx = 0; kx < 3; kx++)
                    p2[yy][kx] = pk2(r[yy][kx], r[yy][kx+1]);

            const ull* w2 = (const ull*)sW2[ci];
            #pragma unroll
            for (int co = 0; co < 16; co++) {
                #pragma unroll
                for (int k = 0; k < 9; k++) {
                    ull wv = w2[co*9 + k];
                    int ky = k / 3, kx = k % 3;
                    acc[co][0] = ffma2(wv, p2[ky  ][kx], acc[co][0]);
                    acc[co][1] = ffma2(wv, p2[ky+1][kx], acc[co][1]);
                }
            }
        }
    }

    int py = y0 + ty*2, px = x0 + tx*2;
    #pragma unroll
    for (int co = 0; co < 16; co++) {
        int oc = cot*16 + co;
        float bv = bias[oc];
        float* ob = g_off2 + (job*OFFC + oc)*HW2;
        float a0, a1, a2, a3;
        upk2(acc[co][0], a0, a1);
        upk2(acc[co][1], a2, a3);
        ob[py*W2 + px      ] = a0 + bv;
        ob[py*W2 + px + 1  ] = a1 + bv;
        ob[(py+1)*W2 + px  ] = a2 + bv;
        ob[(py+1)*W2 + px+1] = a3 + bv;
    }
}

// ---------------------------------------------------------------------------
// 5) bilinear 2x upsample * 2.0 (half-pixel == clamp-to-edge)
// ---------------------------------------------------------------------------
__global__ void k_upsample() {
    int idx = blockIdx.x * blockDim.x + threadIdx.x;
    if (idx >= NJ*OFFC*HW) return;
    int ox = idx & 127;
    int oy = (idx >> 7) & 127;
    int plane = idx >> 14;
    const float* p = g_off2 + plane*HW2;

    float fy = oy*0.5f - 0.25f;
    float fx = ox*0.5f - 0.25f;
    float fy0 = floorf(fy), fx0 = floorf(fx);
    float wy = fy - fy0, wx = fx - fx0;
    int iy = (int)fy0, ix = (int)fx0;
    int y0 = max(0, min(H2-1, iy)),   y1 = max(0, min(H2-1, iy+1));
    int x0 = max(0, min(W2-1, ix)),   x1 = max(0, min(W2-1, ix+1));
    float v = (1.f-wy)*((1.f-wx)*p[y0*W2+x0] + wx*p[y0*W2+x1])
            +      wy *((1.f-wx)*p[y1*W2+x0] + wx*p[y1*W2+x1]);
    g_off2us[idx] = 2.f * v;
}

// ---------------------------------------------------------------------------
// 6) deformable conv (G=8, Cg=8, 3x3, 64->64). Packed over output-channel
//    pairs: acc2[o2] lanes = (o=2*o2, o=2*o2+1); sampled value broadcast.
//    Weight slices for a whole group (9 k) staged per sync.
// ---------------------------------------------------------------------------
__global__ __launch_bounds__(256, 2)
void k_deform(const float* __restrict__ x, float* __restrict__ out, int final_mode) {
    int job = blockIdx.z;
    int b = job >> 2, fi = job & 3;
    int frame = job_frame(fi);

    const float* xf   = x + ((size_t)(b*TT + frame)*CC)*HW;
    const float* offs = (final_mode ? g_off1 : g_off2us) + (size_t)job*OFFC*HW;
    const float2* wt2 = final_mode ? g_waft2 : g_wa1t2;
    float* ob = final_mode ? (out + ((size_t)(b*TT + frame)*CC)*HW)
                           : (g_z1 + (size_t)job*CC*HW);

    int tid = threadIdx.x;
    int px = blockIdx.x*16 + (tid & 15);
    int py = blockIdx.y*16 + (tid >> 4);
    int p  = py*WW + px;

    __shared__ __align__(16) float2 sW2[KK9*256];  // [k][o2*8+c] pairs for current g

    ull acc[32];
    #pragma unroll
    for (int o = 0; o < 32; o++) acc[o] = 0ull;

    for (int g = 0; g < GG; g++) {
        __syncthreads();
        #pragma unroll
        for (int k = 0; k < KK9; k++)
            sW2[k*256 + tid] = wt2[(k*8 + g)*256 + tid];
        __syncthreads();

        const float* xg = xf + (size_t)g*8*HW;
        #pragma unroll
        for (int k = 0; k < KK9; k++) {
            int ch = (g*KK9 + k)*2;
            float dy = offs[ch*HW + p];
            float dx = offs[(ch+1)*HW + p];
            float sy = dy + (float)(py + k/3 - 1);
            float sx = dx + (float)(px + k%3 - 1);
            float fy0 = floorf(sy), fx0 = floorf(sx);
            float wy = sy - fy0, wx = sx - fx0;
            int y0 = (int)fy0, xx0 = (int)fx0;
            int y1 = y0 + 1,   xx1 = xx0 + 1;
            bool vy0 = (unsigned)y0  < HH, vy1 = (unsigned)y1  < HH;
            bool vx0 = (unsigned)xx0 < WW, vx1 = (unsigned)xx1 < WW;
            int y0c = min(max(y0, 0), HH-1), y1c = min(max(y1, 0), HH-1);
            int x0c = min(max(xx0,0), WW-1), x1c = min(max(xx1,0), WW-1);
            float w00 = (vy0 && vx0) ? (1.f-wy)*(1.f-wx) : 0.f;
            float w01 = (vy0 && vx1) ? (1.f-wy)*wx       : 0.f;
            float w10 = (vy1 && vx0) ? wy*(1.f-wx)       : 0.f;
            float w11 = (vy1 && vx1) ? wy*wx             : 0.f;
            int o00 = y0c*WW + x0c, o01 = y0c*WW + x1c;
            int o10 = y1c*WW + x0c, o11 = y1c*WW + x1c;

            ull s2[8];
            #pragma unroll
            for (int c = 0; c < 8; c++) {
                const float* xp = xg + c*HW;
                float s = w00*__ldg(xp + o00) + w01*__ldg(xp + o01)
                        + w10*__ldg(xp + o10) + w11*__ldg(xp + o11);
                s2[c] = pk2(s, s);
            }
            const ulonglong2* w2 = (const ulonglong2*)(sW2 + k*256);
            #pragma unroll
            for (int o2 = 0; o2 < 32; o2++) {
                const ulonglong2* wr = w2 + o2*4;
                ull a = acc[o2];
                #pragma unroll
                for (int c4 = 0; c4 < 4; c4++) {
                    ulonglong2 wp = wr[c4];
                    a = ffma2(wp.x, s2[2*c4    ], a);
                    a = ffma2(wp.y, s2[2*c4 + 1], a);
                }
                acc[o2] = a;
            }
        }
    }
    #pragma unroll
    for (int o2 = 0; o2 < 32; o2++) {
        float v0, v1;
        upk2(acc[o2], v0, v1);
        ob[(2*o2    )*HW + p] = v0;
        ob[(2*o2 + 1)*HW + p] = v1;
    }
}

// ---------------------------------------------------------------------------
// 7) conv5x5 pad2 @128x128, Cin=128, Cout=144, +bias +off2_us -> g_off1
//    packed f32x2, ci chunk 4
// ---------------------------------------------------------------------------
#define CI5 4
__global__ __launch_bounds__(256, 2)
void k_conv5(const float* __restrict__ x, const float* __restrict__ wg,
             const float* __restrict__ bias) {
    int zc  = blockIdx.z;
    int job = zc / 9, cot = zc % 9;
    int b = job >> 2;
    int x0 = blockIdx.x * 32, y0 = blockIdx.y * 32;
    int tx = threadIdx.x, ty = threadIdx.y;
    int tid = ty * 16 + tx;

    __shared__ float  sIn[CI5][36*36];
    __shared__ float2 sW2[CI5][16*25];

    ull acc[16][2];
    #pragma unroll
    for (int i = 0; i < 16; i++) { acc[i][0] = 0ull; acc[i][1] = 0ull; }

    const float* srcZ = g_z1 + (size_t)job*CC*HW;
    const float* srcC = x + ((size_t)(b*TT + TCEN)*CC)*HW;

    for (int c0 = 0; c0 < 2*CC; c0 += CI5) {
        __syncthreads();
        for (int l = tid; l < CI5*36*36; l += 256) {
            int ci = l / (36*36), r = l % (36*36);
            int ly = r / 36, lx = r % 36;
            int cig = c0 + ci;
            const float* src = (cig < CC) ? (srcZ + cig*HW) : (srcC + (cig-CC)*HW);
            int gy = y0 + ly - 2, gx = x0 + lx - 2;
            sIn[ci][r] = (gy >= 0 && gy < HH && gx >= 0 && gx < WW) ? src[gy*WW + gx] : 0.f;
        }
        for (int l = tid; l < CI5*400; l += 256) {
            int ci = l / 400, q = l % 400;
            int co = q / 25, k = q % 25;
            float w = wg[((cot*16 + co)*(2*CC) + c0 + ci)*25 + k];
            sW2[ci][q] = make_float2(w, w);
        }
        __syncthreads();

        int py = ty*2, px = tx*2;
        #pragma unroll
        for (int ci = 0; ci < CI5; ci++) {
            float r[6][6];
            #pragma unroll
            for (int yy = 0; yy < 6; yy++)
                #pragma unroll
                for (int xx = 0; xx < 6; xx++)
                    r[yy][xx] = sIn[ci][(py+yy)*36 + px + xx];

            const ull* w2 = (const ull*)sW2[ci];
            #pragma unroll
            for (int k = 0; k < 25; k++) {
                int ky = k / 5, kx = k % 5;
                ull pt = pk2(r[ky  ][kx], r[ky  ][kx+1]);
                ull pb = pk2(r[ky+1][kx], r[ky+1][kx+1]);
                #pragma unroll
                for (int co = 0; co < 16; co++) {
                    ull wv = w2[co*25 + k];
                    acc[co][0] = ffma2(wv, pt, acc[co][0]);
                    acc[co][1] = ffma2(wv, pb, acc[co][1]);
                }
            }
        }
    }

    int py = y0 + ty*2, px = x0 + tx*2;
    #pragma unroll
    for (int co = 0; co < 16; co++) {
        int oc = cot*16 + co;
        float bv = bias[oc];
        const float* ub = g_off2us + ((size_t)job*OFFC + oc)*HW;
        float*       ob = g_off1   + ((size_t)job*OFFC + oc)*HW;
        int p00 = py*WW + px;
        float a0, a1, a2, a3;
        upk2(acc[co][0], a0, a1);
        upk2(acc[co][1], a2, a3);
        ob[p00       ] = a0 + bv + ub[p00       ];
        ob[p00 + 1   ] = a1 + bv + ub[p00 + 1   ];
        ob[p00 + WW  ] = a2 + bv + ub[p00 + WW  ];
        ob[p00 + WW+1] = a3 + bv + ub[p00 + WW+1];
    }
}

// ---------------------------------------------------------------------------
extern "C" void kernel_launch(void* const* d_in, const int* in_sizes, int n_in,
                              void* d_out, int out_size) {
    const float* x        = (const float*)d_in[0];
    const float* w_off1   = (const float*)d_in[1];
    const float* b_off1   = (const float*)d_in[2];
    const float* w_off2   = (const float*)d_in[3];
    const float* b_off2   = (const float*)d_in[4];
    const float* w_align1 = (const float*)d_in[5];
    const float* w_alignf = (const float*)d_in[6];
    float* out = (float*)d_out;

    k_downsample<<<(BB*TT*CC*HW2 + 255)/256, 256>>>(x);
    k_center<<<(BB*CC*HW + 255)/256, 256>>>(x, out);
    k_wtrans<<<(KK9*GG*32*8 + 255)/256, 256>>>(w_align1, w_alignf);

    dim3 tb(16, 16);
    k_conv3<<<dim3(2, 2, NJ*9), tb>>>(w_off2, b_off2);
    k_upsample<<<(NJ*OFFC*HW + 255)/256, 256>>>();
    k_deform<<<dim3(8, 8, NJ), 256>>>(x, out, 0);
    k_conv5<<<dim3(4, 4, NJ*9), tb>>>(x, w_off1, b_off1);
    k_deform<<<dim3(8, 8, NJ), 256>>>(x, out, 1);
}

// round 11
// speedup vs baseline: 3.0483x; 3.0483x over previous
#include <cuda_runtime.h>
#include <cuda_bf16.h>
#include <math.h>
#include <stdint.h>

#define BB    2
#define TT    5
#define CC    64
#define HH    128
#define WW    128
#define H2    64
#define W2    64
#define GG    8
#define KK9   9
#define OFFC  144
#define TCEN  2
#define NJ    8
#define HW    (HH*WW)
#define HW2   (H2*W2)

// ---- scratch (device globals; no allocations allowed) ----
__device__ float    g_off2[NJ*OFFC*HW2];
__device__ float    g_off2us[NJ*OFFC*HW];
__device__ float    g_z1[NJ*CC*HW];
__device__ float    g_off1[NJ*OFFC*HW];
__device__ float    g_wa1t[CC*CC*KK9];      // deform weights [k][g][o][c]
__device__ float    g_waft[CC*CC*KK9];
// packed (bf16hi<<16 | bf16lo) operands for the mma convs
__device__ uint32_t g_x2p[BB*TT*CC*HW2];    // downsampled frames, packed
__device__ uint32_t g_xcp[BB*CC*HW];        // center frame full-res, packed
__device__ uint32_t g_z1p[NJ*CC*HW];        // z1, packed
__device__ uint32_t g_w5p[OFFC*128*25];
__device__ uint32_t g_w3p[OFFC*128*9];
__device__ int2     g_tab5[128*25];
__device__ int2     g_tab3[128*9];

__device__ __forceinline__ int job_frame(int fi) { return fi + (fi >= TCEN ? 1 : 0); }

__device__ __forceinline__ uint32_t packhl(float v) {
    __nv_bfloat16 h = __float2bfloat16(v);
    __nv_bfloat16 l = __float2bfloat16(v - __bfloat162float(h));
    return ((uint32_t)__bfloat16_as_ushort(h) << 16) | (uint32_t)__bfloat16_as_ushort(l);
}
__device__ __forceinline__ uint32_t smem_u32(const void* p) {
    uint32_t a;
    asm("{ .reg .u64 t; cvta.to.shared.u64 t, %1; cvt.u32.u64 %0, t; }" : "=r"(a) : "l"(p));
    return a;
}
__device__ __forceinline__ void ldmx4(uint32_t* r, uint32_t a) {
    asm volatile("ldmatrix.sync.aligned.m8n8.x4.shared.b16 {%0,%1,%2,%3}, [%4];"
        : "=r"(r[0]), "=r"(r[1]), "=r"(r[2]), "=r"(r[3]) : "r"(a));
}
__device__ __forceinline__ void ldmx2(uint32_t* r, uint32_t a) {
    asm volatile("ldmatrix.sync.aligned.m8n8.x2.shared.b16 {%0,%1}, [%2];"
        : "=r"(r[0]), "=r"(r[1]) : "r"(a));
}
__device__ __forceinline__ void mmabf(float* d, const uint32_t* a, const uint32_t* b) {
    asm volatile("mma.sync.aligned.m16n8k16.row.col.f32.bf16.bf16.f32 "
        "{%0,%1,%2,%3}, {%4,%5,%6,%7}, {%8,%9}, {%0,%1,%2,%3};"
        : "+f"(d[0]), "+f"(d[1]), "+f"(d[2]), "+f"(d[3])
        : "r"(a[0]), "r"(a[1]), "r"(a[2]), "r"(a[3]), "r"(b[0]), "r"(b[1]));
}

// ===========================================================================
// 1) 2x2 average pool + hi/lo pack: x -> g_x2p
// ===========================================================================
__global__ void k_downsample(const float* __restrict__ x) {
    int idx = blockIdx.x * blockDim.x + threadIdx.x;
    if (idx >= BB*TT*CC*HW2) return;
    int xx = idx & 63;
    int yy = (idx >> 6) & 63;
    int c  = (idx >> 12) & 63;
    int bt = idx >> 18;
    const float* s = x + ((size_t)bt*CC + c)*HW + (yy*2)*WW + xx*2;
    g_x2p[idx] = packhl(0.25f * (s[0] + s[1] + s[WW] + s[WW+1]));
}

// ===========================================================================
// 2) center frame: passthrough to out + packed copy
// ===========================================================================
__global__ void k_center(const float* __restrict__ x, float* __restrict__ out) {
    int idx = blockIdx.x * blockDim.x + threadIdx.x;
    if (idx >= BB*CC*HW) return;
    int b    = idx >> 20;
    int rest = idx & ((1 << 20) - 1);
    size_t off = ((size_t)(b*TT + TCEN) << 20) + rest;
    float v = x[off];
    out[off] = v;
    g_xcp[idx] = packhl(v);
}

// ===========================================================================
// 3) transpose deform weights -> [k][g][o][c]
// ===========================================================================
__global__ void k_wtrans(const float* __restrict__ w1, const float* __restrict__ wf) {
    int idx = blockIdx.x * blockDim.x + threadIdx.x;
    if (idx >= CC*CC*KK9) return;
    int c = idx & 7;
    int o = (idx >> 3) & 63;
    int g = (idx >> 9) & 7;
    int k = idx >> 12;
    int src = (o*CC + g*8 + c)*KK9 + k;
    g_wa1t[idx] = w1[src];
    g_waft[idx] = wf[src];
}

// ===========================================================================
// 3b) generic hi/lo pack, and im2col tap tables
// ===========================================================================
__global__ void k_pack(const float* __restrict__ src, uint32_t* __restrict__ dst, int n) {
    int i = blockIdx.x * blockDim.x + threadIdx.x;
    if (i < n) dst[i] = packhl(src[i]);
}
__global__ void k_tab() {
    int k = blockIdx.x * blockDim.x + threadIdx.x;
    if (k < 128*25) {
        int ci = k / 25, t = k % 25, ky = t / 5, kx = t % 5;
        g_tab5[k] = make_int2((ci & 63)*HW + (ky - 2)*WW + (kx - 2),
                              (ci >= 64 ? 1 : 0) | (ky << 8) | (kx << 16));
    }
    if (k < 128*9) {
        int ci = k / 9, t = k % 9, ky = t / 3, kx = t % 3;
        g_tab3[k] = make_int2((ci & 63)*HW2 + (ky - 1)*W2 + (kx - 1),
                              (ci >= 64 ? 1 : 0) | (ky << 8) | (kx << 16));
    }
}

// ===========================================================================
// 4) mma.sync implicit-GEMM conv (both offset convs), bf16 hi/lo 3-pass.
//    D[M=128px][N=144oc] = A[M][K] * B[N][K]^T ; K = 128ci * taps.
//    CTA 256 thr = 8 warps: 4 along M (32 rows), 2 along N (72 cols).
// ===========================================================================
#define SA 40   // smem row stride in bf16 units (80B): conflict-free ldmatrix
template<bool IS5>
__global__ __launch_bounds__(256) void k_convMMA(
    const uint32_t* __restrict__ pZall, const uint32_t* __restrict__ pCall,
    const uint32_t* __restrict__ wp, const float* __restrict__ bias)
{
    constexpr int KTAP = IS5 ? 25 : 9;
    constexpr int R    = IS5 ? 2 : 1;
    constexpr int KTOT = 128 * KTAP;
    constexpr int NCH  = KTOT / 32;
    constexpr int Wimg = IS5 ? 128 : 64;
    constexpr int Himg = Wimg;
    constexpr int LGW  = IS5 ? 7 : 6;

    __shared__ __align__(16) unsigned short AsH[128*SA], AsL[128*SA];
    __shared__ __align__(16) unsigned short BsH[144*SA], BsL[144*SA];

    int tid = threadIdx.x, lane = tid & 31, w = tid >> 5;
    int wm = w & 3, wn = w >> 2;
    int job = blockIdx.y, b = job >> 2, fi = job & 3;
    int frame = job_frame(fi);
    int tileBase = blockIdx.x * 128;

    const uint32_t* pZ;
    const uint32_t* pC;
    if (IS5) { pZ = pZall + (size_t)job*CC*HW;
               pC = pCall + (size_t)b*CC*HW; }
    else     { pZ = pZall + (size_t)(b*TT + frame)*CC*HW2;
               pC = pCall + (size_t)(b*TT + TCEN )*CC*HW2; }
    const int2* tab = IS5 ? g_tab5 : g_tab3;

    float acc[2][9][4];
    #pragma unroll
    for (int mt = 0; mt < 2; mt++)
        #pragma unroll
        for (int j = 0; j < 9; j++)
            #pragma unroll
            for (int q = 0; q < 4; q++) acc[mt][j][q] = 0.f;

    uint32_t aHb = smem_u32(AsH), aLb = smem_u32(AsL);
    uint32_t bHb = smem_u32(BsH), bLb = smem_u32(BsL);
    int ar = (lane & 7) + ((lane >> 3) & 1) * 8;
    int ac = ((lane >> 4) & 1) * 8;
    uint32_t aOff[2];
    #pragma unroll
    for (int mt = 0; mt < 2; mt++)
        aOff[mt] = (uint32_t)(((wm*32 + mt*16 + ar)*SA + ac) * 2);
    uint32_t bCom = (uint32_t)((((lane & 7))*SA + ((lane >> 3) & 1) * 8) * 2);

    for (int c = 0; c < NCH; c++) {
        int k0 = c * 32;
        __syncthreads();

        // ---- stage A: warp w handles kk in [4w, 4w+4), lanes cover 128 px
        int kk0 = w * 4;
        int2 e0 = tab[k0+kk0], e1 = tab[k0+kk0+1], e2 = tab[k0+kk0+2], e3 = tab[k0+kk0+3];
        #pragma unroll
        for (int pp = 0; pp < 4; pp++) {
            int m = lane + pp * 32;
            int pixel = tileBase + m;
            int py = pixel >> LGW, px = pixel & (Wimg - 1);
            uint32_t u[4];
            int2 ee[4] = {e0, e1, e2, e3};
            #pragma unroll
            for (int q = 0; q < 4; q++) {
                int ky = (ee[q].y >> 8) & 0xFF, kx = (ee[q].y >> 16) & 0xFF;
                int yy = py + ky - R, xx = px + kx - R;
                u[q] = 0u;
                if ((unsigned)yy < (unsigned)Himg && (unsigned)xx < (unsigned)Wimg)
                    u[q] = __ldg(((ee[q].y & 1) ? pC : pZ) + ee[q].x + pixel);
            }
            uint32_t* dH = (uint32_t*)(AsH + m*SA + kk0);
            uint32_t* dL = (uint32_t*)(AsL + m*SA + kk0);
            dH[0] = (u[0] >> 16) | (u[1] & 0xFFFF0000u);
            dH[1] = (u[2] >> 16) | (u[3] & 0xFFFF0000u);
            dL[0] = (u[0] & 0xFFFFu) | (u[1] << 16);
            dL[1] = (u[2] & 0xFFFFu) | (u[3] << 16);
        }
        // ---- stage B: 144 x 32 weights
        #pragma unroll
        for (int i = 0; i < 9; i++) {
            int l = tid + i * 256;              // < 2304
            int n = l >> 4, kp = l & 15;
            uint32_t u0 = __ldg(wp + (size_t)n*KTOT + k0 + 2*kp);
            uint32_t u1 = __ldg(wp + (size_t)n*KTOT + k0 + 2*kp + 1);
            *(uint32_t*)(BsH + n*SA + 2*kp) = (u0 >> 16) | (u1 & 0xFFFF0000u);
            *(uint32_t*)(BsL + n*SA + 2*kp) = (u0 & 0xFFFFu) | (u1 << 16);
        }
        __syncthreads();

        // ---- compute: 2 k16 halves x 9 n8 tiles x (hh, hl, lh)
        #pragma unroll
        for (int kh = 0; kh < 2; kh++) {
            uint32_t aH[2][4], aL[2][4];
            #pragma unroll
            for (int mt = 0; mt < 2; mt++) {
                ldmx4(aH[mt], aHb + aOff[mt] + kh*32);
                ldmx4(aL[mt], aLb + aOff[mt] + kh*32);
            }
            #pragma unroll
            for (int j = 0; j < 9; j++) {
                uint32_t boff = (uint32_t)((wn*72 + j*8)*SA*2) + bCom + kh*32;
                uint32_t bH[2], bL[2];
                ldmx2(bH, bHb + boff);
                ldmx2(bL, bLb + boff);
                #pragma unroll
                for (int mt = 0; mt < 2; mt++) {
                    mmabf(acc[mt][j], aH[mt], bH);
                    mmabf(acc[mt][j], aH[mt], bL);
                    mmabf(acc[mt][j], aL[mt], bH);
                }
            }
        }
    }

    // ---- epilogue
    int r0 = lane >> 2, cp = (lane & 3) * 2;
    #pragma unroll
    for (int mt = 0; mt < 2; mt++) {
        #pragma unroll
        for (int j = 0; j < 9; j++) {
            int col = wn*72 + j*8 + cp;
            int rowA = tileBase + wm*32 + mt*16 + r0;
            float b0 = __ldg(bias + col), b1 = __ldg(bias + col + 1);
            #pragma unroll
            for (int h = 0; h < 2; h++) {
                int pix = rowA + h*8;
                float v0 = acc[mt][j][2*h    ] + b0;
                float v1 = acc[mt][j][2*h + 1] + b1;
                if (IS5) {
                    size_t i0 = (size_t)job*OFFC*HW + (size_t)col*HW + pix;
                    size_t i1 = i0 + HW;
                    g_off1[i0] = v0 + g_off2us[i0];
                    g_off1[i1] = v1 + g_off2us[i1];
                } else {
                    size_t i0 = (size_t)job*OFFC*HW2 + (size_t)col*HW2 + pix;
                    g_off2[i0      ] = v0;
                    g_off2[i0 + HW2] = v1;
                }
            }
        }
    }
}

// ===========================================================================
// 5) bilinear 2x upsample * 2.0 (half-pixel == clamp-to-edge)
// ===========================================================================
__global__ void k_upsample() {
    int idx = blockIdx.x * blockDim.x + threadIdx.x;
    if (idx >= NJ*OFFC*HW) return;
    int ox = idx & 127;
    int oy = (idx >> 7) & 127;
    int plane = idx >> 14;
    const float* p = g_off2 + plane*HW2;

    float fy = oy*0.5f - 0.25f;
    float fx = ox*0.5f - 0.25f;
    float fy0 = floorf(fy), fx0 = floorf(fx);
    float wy = fy - fy0, wx = fx - fx0;
    int iy = (int)fy0, ix = (int)fx0;
    int y0 = max(0, min(H2-1, iy)),   y1 = max(0, min(H2-1, iy+1));
    int x0 = max(0, min(W2-1, ix)),   x1 = max(0, min(W2-1, ix+1));
    float v = (1.f-wy)*((1.f-wx)*p[y0*W2+x0] + wx*p[y0*W2+x1])
            +      wy *((1.f-wx)*p[y1*W2+x0] + wx*p[y1*W2+x1]);
    g_off2us[idx] = 2.f * v;
}

// ===========================================================================
// 6) deformable conv (R2 scalar version — known-good)
// ===========================================================================
__global__ void k_deform(const float* __restrict__ x, float* __restrict__ out, int final_mode) {
    int job = blockIdx.z;
    int b = job >> 2, fi = job & 3;
    int frame = job_frame(fi);

    const float* xf   = x + ((size_t)(b*TT + frame)*CC)*HW;
    const float* offs = (final_mode ? g_off1 : g_off2us) + (size_t)job*OFFC*HW;
    const float* wt   = final_mode ? g_waft : g_wa1t;
    float* ob = final_mode ? (out + ((size_t)(b*TT + frame)*CC)*HW)
                           : (g_z1 + (size_t)job*CC*HW);

    int tid = threadIdx.x;
    int px = blockIdx.x*16 + (tid & 15);
    int py = blockIdx.y*16 + (tid >> 4);
    int p  = py*WW + px;

    __shared__ float sW[512];
    float acc[64];
    #pragma unroll
    for (int o = 0; o < 64; o++) acc[o] = 0.f;

    for (int g = 0; g < GG; g++) {
        for (int k = 0; k < KK9; k++) {
            __syncthreads();
            const float* ws = wt + (k*8 + g)*512;
            sW[tid]       = ws[tid];
            sW[tid + 256] = ws[tid + 256];
            __syncthreads();

            int ch = (g*KK9 + k)*2;
            float dy = offs[ch*HW + p];
            float dx = offs[(ch+1)*HW + p];
            float sy = dy + (float)(py + k/3 - 1);
            float sx = dx + (float)(px + k%3 - 1);
            float fy0 = floorf(sy), fx0 = floorf(sx);
            float wy = sy - fy0, wx = sx - fx0;
            int y0 = (int)fy0, xx0 = (int)fx0;
            int y1 = y0 + 1,   xx1 = xx0 + 1;
            bool vy0 = (unsigned)y0  < HH, vy1 = (unsigned)y1  < HH;
            bool vx0 = (unsigned)xx0 < WW, vx1 = (unsigned)xx1 < WW;
            int y0c = min(max(y0, 0), HH-1), y1c = min(max(y1, 0), HH-1);
            int x0c = min(max(xx0,0), WW-1), x1c = min(max(xx1,0), WW-1);
            float w00 = (vy0 && vx0) ? (1.f-wy)*(1.f-wx) : 0.f;
            float w01 = (vy0 && vx1) ? (1.f-wy)*wx       : 0.f;
            float w10 = (vy1 && vx0) ? wy*(1.f-wx)       : 0.f;
            float w11 = (vy1 && vx1) ? wy*wx             : 0.f;
            int o00 = y0c*WW + x0c, o01 = y0c*WW + x1c;
            int o10 = y1c*WW + x0c, o11 = y1c*WW + x1c;

            float s[8];
            const float* xg = xf + (size_t)g*8*HW;
            #pragma unroll
            for (int c = 0; c < 8; c++) {
                const float* xp = xg + c*HW;
                s[c] = w00*__ldg(xp + o00) + w01*__ldg(xp + o01)
                     + w10*__ldg(xp + o10) + w11*__ldg(xp + o11);
            }
            #pragma unroll
            for (int o = 0; o < 64; o++) {
                const float* wr = sW + o*8;
                acc[o] += wr[0]*s[0] + wr[1]*s[1] + wr[2]*s[2] + wr[3]*s[3]
                        + wr[4]*s[4] + wr[5]*s[5] + wr[6]*s[6] + wr[7]*s[7];
            }
        }
    }
    #pragma unroll
    for (int o = 0; o < 64; o++) ob[o*HW + p] = acc[o];
}

// ===========================================================================
extern "C" void kernel_launch(void* const* d_in, const int* in_sizes, int n_in,
                              void* d_out, int out_size) {
    const float* x        = (const float*)d_in[0];
    const float* w_off1   = (const float*)d_in[1];
    const float* b_off1   = (const float*)d_in[2];
    const float* w_off2   = (const float*)d_in[3];
    const float* b_off2   = (const float*)d_in[4];
    const float* w_align1 = (const float*)d_in[5];
    const float* w_alignf = (const float*)d_in[6];
    float* out = (float*)d_out;

    // ALL device-symbol pointers via cudaGetSymbolAddress (R9 bug: passing
    // __device__ symbols directly from host gives the host shadow address).
    uint32_t* w5p = nullptr; uint32_t* w3p = nullptr;
    uint32_t* z1p = nullptr; float* z1f = nullptr;
    uint32_t* x2p = nullptr; uint32_t* xcp = nullptr;
    cudaGetSymbolAddress((void**)&w5p, g_w5p);
    cudaGetSymbolAddress((void**)&w3p, g_w3p);
    cudaGetSymbolAddress((void**)&z1p, g_z1p);
    cudaGetSymbolAddress((void**)&z1f, g_z1);
    cudaGetSymbolAddress((void**)&x2p, g_x2p);
    cudaGetSymbolAddress((void**)&xcp, g_xcp);

    k_downsample<<<(BB*TT*CC*HW2 + 255)/256, 256>>>(x);
    k_center<<<(BB*CC*HW + 255)/256, 256>>>(x, out);
    k_wtrans<<<(CC*CC*KK9 + 255)/256, 256>>>(w_align1, w_alignf);
    k_pack<<<(OFFC*128*25 + 255)/256, 256>>>(w_off1, w5p, OFFC*128*25);
    k_pack<<<(OFFC*128*9  + 255)/256, 256>>>(w_off2, w3p, OFFC*128*9);
    k_tab<<<(128*25 + 255)/256, 256>>>();

    k_convMMA<false><<<dim3(HW2/128, NJ), 256>>>(x2p, x2p, w3p, b_off2);
    k_upsample<<<(NJ*OFFC*HW + 255)/256, 256>>>();
    k_deform<<<dim3(8, 8, NJ), 256>>>(x, out, 0);
    k_pack<<<(NJ*CC*HW + 255)/256, 256>>>(z1f, z1p, NJ*CC*HW);
    k_convMMA<true><<<dim3(HW/128, NJ), 256>>>(z1p, xcp, w5p, b_off1);
    k_deform<<<dim3(8, 8, NJ), 256>>>(x, out, 1);
}

// round 12
// speedup vs baseline: 4.1493x; 1.3612x over previous
#include <cuda_runtime.h>
#include <cuda_bf16.h>
#include <math.h>
#include <stdint.h>

#define BB    2
#define TT    5
#define CC    64
#define HH    128
#define WW    128
#define H2    64
#define W2    64
#define GG    8
#define KK9   9
#define OFFC  144
#define TCEN  2
#define NJ    8
#define HW    (HH*WW)
#define HW2   (H2*W2)

// ---- scratch (device globals; no allocations allowed) ----
__device__ float    g_off2[NJ*OFFC*HW2];
__device__ float    g_off2us[NJ*OFFC*HW];
__device__ float    g_off1[NJ*OFFC*HW];
// packed (bf16hi<<16 | bf16lo) operands
__device__ uint32_t g_x2p[BB*TT*CC*HW2];    // downsampled frames, packed
__device__ uint32_t g_xcp[BB*CC*HW];        // center frame full-res, packed
__device__ uint32_t g_z1p[NJ*CC*HW];        // z1, packed (written by deform stage0)
__device__ uint32_t g_w5p[OFFC*128*25];
__device__ uint32_t g_w3p[OFFC*128*9];
__device__ uint32_t g_wd1p[72*64*8];        // deform weights packed [pair][o][c]
__device__ uint32_t g_wdfp[72*64*8];
__device__ int2     g_tab5[128*25];
__device__ int2     g_tab3[128*9];

__device__ __forceinline__ int job_frame(int fi) { return fi + (fi >= TCEN ? 1 : 0); }

__device__ __forceinline__ uint32_t packhl(float v) {
    __nv_bfloat16 h = __float2bfloat16(v);
    __nv_bfloat16 l = __float2bfloat16(v - __bfloat162float(h));
    return ((uint32_t)__bfloat16_as_ushort(h) << 16) | (uint32_t)__bfloat16_as_ushort(l);
}
__device__ __forceinline__ uint32_t smem_u32(const void* p) {
    uint32_t a;
    asm("{ .reg .u64 t; cvta.to.shared.u64 t, %1; cvt.u32.u64 %0, t; }" : "=r"(a) : "l"(p));
    return a;
}
__device__ __forceinline__ void ldmx4(uint32_t* r, uint32_t a) {
    asm volatile("ldmatrix.sync.aligned.m8n8.x4.shared.b16 {%0,%1,%2,%3}, [%4];"
        : "=r"(r[0]), "=r"(r[1]), "=r"(r[2]), "=r"(r[3]) : "r"(a));
}
__device__ __forceinline__ void ldmx2(uint32_t* r, uint32_t a) {
    asm volatile("ldmatrix.sync.aligned.m8n8.x2.shared.b16 {%0,%1}, [%2];"
        : "=r"(r[0]), "=r"(r[1]) : "r"(a));
}
__device__ __forceinline__ void mmabf(float* d, const uint32_t* a, const uint32_t* b) {
    asm volatile("mma.sync.aligned.m16n8k16.row.col.f32.bf16.bf16.f32 "
        "{%0,%1,%2,%3}, {%4,%5,%6,%7}, {%8,%9}, {%0,%1,%2,%3};"
        : "+f"(d[0]), "+f"(d[1]), "+f"(d[2]), "+f"(d[3])
        : "r"(a[0]), "r"(a[1]), "r"(a[2]), "r"(a[3]), "r"(b[0]), "r"(b[1]));
}

// ===========================================================================
// 1) 2x2 average pool + hi/lo pack
// ===========================================================================
__global__ void k_downsample(const float* __restrict__ x) {
    int idx = blockIdx.x * blockDim.x + threadIdx.x;
    if (idx >= BB*TT*CC*HW2) return;
    int xx = idx & 63;
    int yy = (idx >> 6) & 63;
    int c  = (idx >> 12) & 63;
    int bt = idx >> 18;
    const float* s = x + ((size_t)bt*CC + c)*HW + (yy*2)*WW + xx*2;
    g_x2p[idx] = packhl(0.25f * (s[0] + s[1] + s[WW] + s[WW+1]));
}

// ===========================================================================
// 2) center frame: passthrough + packed copy
// ===========================================================================
__global__ void k_center(const float* __restrict__ x, float* __restrict__ out) {
    int idx = blockIdx.x * blockDim.x + threadIdx.x;
    if (idx >= BB*CC*HW) return;
    int b    = idx >> 20;
    int rest = idx & ((1 << 20) - 1);
    size_t off = ((size_t)(b*TT + TCEN) << 20) + rest;
    float v = x[off];
    out[off] = v;
    g_xcp[idx] = packhl(v);
}

// ===========================================================================
// 3) deform weight pack: [pair=g*9+k][o][c] (bf16 hi/lo packed)
// ===========================================================================
__global__ void k_wdeform(const float* __restrict__ w1, const float* __restrict__ wf) {
    int idx = blockIdx.x * blockDim.x + threadIdx.x;
    if (idx >= 72*64*8) return;
    int c = idx & 7;
    int o = (idx >> 3) & 63;
    int p = idx >> 9;
    int g = p / 9, k = p - g*9;
    int src = (o*CC + g*8 + c)*KK9 + k;
    g_wd1p[idx] = packhl(w1[src]);
    g_wdfp[idx] = packhl(wf[src]);
}

// ===========================================================================
// 3b) generic hi/lo pack + im2col tap tables
// ===========================================================================
__global__ void k_pack(const float* __restrict__ src, uint32_t* __restrict__ dst, int n) {
    int i = blockIdx.x * blockDim.x + threadIdx.x;
    if (i < n) dst[i] = packhl(src[i]);
}
__global__ void k_tab() {
    int k = blockIdx.x * blockDim.x + threadIdx.x;
    if (k < 128*25) {
        int ci = k / 25, t = k % 25, ky = t / 5, kx = t % 5;
        g_tab5[k] = make_int2((ci & 63)*HW + (ky - 2)*WW + (kx - 2),
                              (ci >= 64 ? 1 : 0) | (ky << 8) | (kx << 16));
    }
    if (k < 128*9) {
        int ci = k / 9, t = k % 9, ky = t / 3, kx = t % 3;
        g_tab3[k] = make_int2((ci & 63)*HW2 + (ky - 1)*W2 + (kx - 1),
                              (ci >= 64 ? 1 : 0) | (ky << 8) | (kx << 16));
    }
}

// ===========================================================================
// 4) mma.sync implicit-GEMM conv (both offset convs), bf16 hi/lo 3-pass.
// ===========================================================================
#define SA 40
template<bool IS5>
__global__ __launch_bounds__(256) void k_convMMA(
    const uint32_t* __restrict__ pZall, const uint32_t* __restrict__ pCall,
    const uint32_t* __restrict__ wp, const float* __restrict__ bias)
{
    constexpr int KTAP = IS5 ? 25 : 9;
    constexpr int R    = IS5 ? 2 : 1;
    constexpr int KTOT = 128 * KTAP;
    constexpr int NCH  = KTOT / 32;
    constexpr int Wimg = IS5 ? 128 : 64;
    constexpr int Himg = Wimg;
    constexpr int LGW  = IS5 ? 7 : 6;

    __shared__ __align__(16) unsigned short AsH[128*SA], AsL[128*SA];
    __shared__ __align__(16) unsigned short BsH[144*SA], BsL[144*SA];

    int tid = threadIdx.x, lane = tid & 31, w = tid >> 5;
    int wm = w & 3, wn = w >> 2;
    int job = blockIdx.y, b = job >> 2, fi = job & 3;
    int frame = job_frame(fi);
    int tileBase = blockIdx.x * 128;

    const uint32_t* pZ;
    const uint32_t* pC;
    if (IS5) { pZ = pZall + (size_t)job*CC*HW;
               pC = pCall + (size_t)b*CC*HW; }
    else     { pZ = pZall + (size_t)(b*TT + frame)*CC*HW2;
               pC = pCall + (size_t)(b*TT + TCEN )*CC*HW2; }
    const int2* tab = IS5 ? g_tab5 : g_tab3;

    float acc[2][9][4];
    #pragma unroll
    for (int mt = 0; mt < 2; mt++)
        #pragma unroll
        for (int j = 0; j < 9; j++)
            #pragma unroll
            for (int q = 0; q < 4; q++) acc[mt][j][q] = 0.f;

    uint32_t aHb = smem_u32(AsH), aLb = smem_u32(AsL);
    uint32_t bHb = smem_u32(BsH), bLb = smem_u32(BsL);
    int ar = (lane & 7) + ((lane >> 3) & 1) * 8;
    int ac = ((lane >> 4) & 1) * 8;
    uint32_t aOff[2];
    #pragma unroll
    for (int mt = 0; mt < 2; mt++)
        aOff[mt] = (uint32_t)(((wm*32 + mt*16 + ar)*SA + ac) * 2);
    uint32_t bCom = (uint32_t)((((lane & 7))*SA + ((lane >> 3) & 1) * 8) * 2);

    for (int c = 0; c < NCH; c++) {
        int k0 = c * 32;
        __syncthreads();

        int kk0 = w * 4;
        int2 e0 = tab[k0+kk0], e1 = tab[k0+kk0+1], e2 = tab[k0+kk0+2], e3 = tab[k0+kk0+3];
        #pragma unroll
        for (int pp = 0; pp < 4; pp++) {
            int m = lane + pp * 32;
            int pixel = tileBase + m;
            int py = pixel >> LGW, px = pixel & (Wimg - 1);
            uint32_t u[4];
            int2 ee[4] = {e0, e1, e2, e3};
            #pragma unroll
            for (int q = 0; q < 4; q++) {
                int ky = (ee[q].y >> 8) & 0xFF, kx = (ee[q].y >> 16) & 0xFF;
                int yy = py + ky - R, xx = px + kx - R;
                u[q] = 0u;
                if ((unsigned)yy < (unsigned)Himg && (unsigned)xx < (unsigned)Wimg)
                    u[q] = __ldg(((ee[q].y & 1) ? pC : pZ) + ee[q].x + pixel);
            }
            uint32_t* dH = (uint32_t*)(AsH + m*SA + kk0);
            uint32_t* dL = (uint32_t*)(AsL + m*SA + kk0);
            dH[0] = (u[0] >> 16) | (u[1] & 0xFFFF0000u);
            dH[1] = (u[2] >> 16) | (u[3] & 0xFFFF0000u);
            dL[0] = (u[0] & 0xFFFFu) | (u[1] << 16);
            dL[1] = (u[2] & 0xFFFFu) | (u[3] << 16);
        }
        #pragma unroll
        for (int i = 0; i < 9; i++) {
            int l = tid + i * 256;
            int n = l >> 4, kp = l & 15;
            uint32_t u0 = __ldg(wp + (size_t)n*KTOT + k0 + 2*kp);
            uint32_t u1 = __ldg(wp + (size_t)n*KTOT + k0 + 2*kp + 1);
            *(uint32_t*)(BsH + n*SA + 2*kp) = (u0 >> 16) | (u1 & 0xFFFF0000u);
            *(uint32_t*)(BsL + n*SA + 2*kp) = (u0 & 0xFFFFu) | (u1 << 16);
        }
        __syncthreads();

        #pragma unroll
        for (int kh = 0; kh < 2; kh++) {
            uint32_t aH[2][4], aL[2][4];
            #pragma unroll
            for (int mt = 0; mt < 2; mt++) {
                ldmx4(aH[mt], aHb + aOff[mt] + kh*32);
                ldmx4(aL[mt], aLb + aOff[mt] + kh*32);
            }
            #pragma unroll
            for (int j = 0; j < 9; j++) {
                uint32_t boff = (uint32_t)((wn*72 + j*8)*SA*2) + bCom + kh*32;
                uint32_t bH[2], bL[2];
                ldmx2(bH, bHb + boff);
                ldmx2(bL, bLb + boff);
                #pragma unroll
                for (int mt = 0; mt < 2; mt++) {
                    mmabf(acc[mt][j], aH[mt], bH);
                    mmabf(acc[mt][j], aH[mt], bL);
                    mmabf(acc[mt][j], aL[mt], bH);
                }
            }
        }
    }

    int r0 = lane >> 2, cp = (lane & 3) * 2;
    #pragma unroll
    for (int mt = 0; mt < 2; mt++) {
        #pragma unroll
        for (int j = 0; j < 9; j++) {
            int col = wn*72 + j*8 + cp;
            int rowA = tileBase + wm*32 + mt*16 + r0;
            float b0 = __ldg(bias + col), b1 = __ldg(bias + col + 1);
            #pragma unroll
            for (int h = 0; h < 2; h++) {
                int pix = rowA + h*8;
                float v0 = acc[mt][j][2*h    ] + b0;
                float v1 = acc[mt][j][2*h + 1] + b1;
                if (IS5) {
                    size_t i0 = (size_t)job*OFFC*HW + (size_t)col*HW + pix;
                    size_t i1 = i0 + HW;
                    g_off1[i0] = v0 + g_off2us[i0];
                    g_off1[i1] = v1 + g_off2us[i1];
                } else {
                    size_t i0 = (size_t)job*OFFC*HW2 + (size_t)col*HW2 + pix;
                    g_off2[i0      ] = v0;
                    g_off2[i0 + HW2] = v1;
                }
            }
        }
    }
}

// ===========================================================================
// 5) 2x bilinear upsample * 2.0, fixed weights {0.25,0.75}, 2x2 quad/thread
// ===========================================================================
__global__ void k_upsample2() {
    int idx = blockIdx.x * blockDim.x + threadIdx.x;
    if (idx >= NJ*OFFC*HW2) return;
    int j = idx & 63;
    int i = (idx >> 6) & 63;
    int plane = idx >> 12;
    const float* p = g_off2 + (size_t)plane*HW2;

    int im1 = max(i-1, 0), ip1 = min(i+1, H2-1);
    int jm1 = max(j-1, 0), jp1 = min(j+1, W2-1);
    float vtl = p[im1*W2+jm1], vtc = p[im1*W2+j], vtr = p[im1*W2+jp1];
    float vml = p[i  *W2+jm1], vmc = p[i  *W2+j], vmr = p[i  *W2+jp1];
    float vbl = p[ip1*W2+jm1], vbc = p[ip1*W2+j], vbr = p[ip1*W2+jp1];

    float h0t = 0.25f*vtl + 0.75f*vtc, h1t = 0.75f*vtc + 0.25f*vtr;
    float h0m = 0.25f*vml + 0.75f*vmc, h1m = 0.75f*vmc + 0.25f*vmr;
    float h0b = 0.25f*vbl + 0.75f*vbc, h1b = 0.75f*vbc + 0.25f*vbr;

    float* d = g_off2us + (size_t)plane*HW;
    float2 r0 = make_float2(2.f*(0.25f*h0t + 0.75f*h0m), 2.f*(0.25f*h1t + 0.75f*h1m));
    float2 r1 = make_float2(2.f*(0.75f*h0m + 0.25f*h0b), 2.f*(0.75f*h1m + 0.25f*h1b));
    *(float2*)(d + (2*i  )*WW + 2*j) = r0;
    *(float2*)(d + (2*i+1)*WW + 2*j) = r1;
}

// ===========================================================================
// 6) deformable conv via mma.sync: out[px,o] = samp[px,K] * W[K,o], K=576.
//    CTA 128 px, K-chunks of 16 (two (g,k) pairs x 8 ch), bf16 hi/lo 3-pass.
//    Epilogue transposes through smem for coalesced px-major stores.
//    final_mode=0 -> g_z1p (packed); final_mode=1 -> out (float).
// ===========================================================================
#define DSA 24
__global__ __launch_bounds__(256) void k_deformMMA(
    const float* __restrict__ x, float* __restrict__ out,
    const uint32_t* __restrict__ wpk, int final_mode)
{
    __shared__ __align__(16) char smem[64*132*4];
    unsigned short* AsH = (unsigned short*)smem;          // 128*24
    unsigned short* AsL = AsH + 128*DSA;                  // 128*24
    unsigned short* BsH = AsL + 128*DSA;                  // 64*24
    unsigned short* BsL = BsH + 64*DSA;                   // 64*24  (tot 18432B)
    float* sOut = (float*)smem;                           // 64*132 (33792B)

    int tid = threadIdx.x, lane = tid & 31, w = tid >> 5;
    int wm = w & 3, wn = w >> 2;
    int job = blockIdx.y, b = job >> 2, fi = job & 3;
    int frame = job_frame(fi);
    int tileBase = blockIdx.x * 128;

    const float* xf   = x + ((size_t)(b*TT + frame)*CC)*HW;
    const float* offs = (final_mode ? g_off1 : g_off2us) + (size_t)job*OFFC*HW;

    int m   = tid & 127;            // pixel-local
    int sel = tid >> 7;             // which pair of the chunk
    int pixel = tileBase + m;
    int py = pixel >> 7, px = pixel & 127;

    // B staging role
    int bo = tid & 63, bhalf = tid >> 6;       // 0..3
    int bpr = bhalf >> 1, bcq = (bhalf & 1)*4;

    float acc[2][4][4];
    #pragma unroll
    for (int mt = 0; mt < 2; mt++)
        #pragma unroll
        for (int j = 0; j < 4; j++)
            #pragma unroll
            for (int q = 0; q < 4; q++) acc[mt][j][q] = 0.f;

    uint32_t aHb = smem_u32(AsH), aLb = smem_u32(AsL);
    uint32_t bHb = smem_u32(BsH), bLb = smem_u32(BsL);
    int ar = (lane & 7) + ((lane >> 3) & 1) * 8;
    int ac = ((lane >> 4) & 1) * 8;
    uint32_t aOff[2];
    #pragma unroll
    for (int mt = 0; mt < 2; mt++)
        aOff[mt] = (uint32_t)(((wm*32 + mt*16 + ar)*DSA + ac) * 2);
    uint32_t bCom = (uint32_t)((((lane & 7))*DSA + ((lane >> 3) & 1) * 8) * 2);

    #pragma unroll 1
    for (int ch = 0; ch < 36; ch++) {
        int p0 = ch * 2;
        __syncthreads();

        // ---- stage A: sample 8 channels for pair (p0+sel) at my pixel
        {
            int p = p0 + sel;
            int g = p / 9, k = p - g*9;
            float dy = __ldg(offs + (size_t)(2*p)*HW + pixel);
            float dx = __ldg(offs + (size_t)(2*p+1)*HW + pixel);
            float sy = dy + (float)(py + k/3 - 1);
            float sx = dx + (float)(px + (k - (k/3)*3) - 1);
            float fy0 = floorf(sy), fx0 = floorf(sx);
            float wy = sy - fy0, wx = sx - fx0;
            int y0 = (int)fy0, xx0 = (int)fx0;
            int y1 = y0 + 1,   xx1 = xx0 + 1;
            bool vy0 = (unsigned)y0  < HH, vy1 = (unsigned)y1  < HH;
            bool vx0 = (unsigned)xx0 < WW, vx1 = (unsigned)xx1 < WW;
            int y0c = min(max(y0, 0), HH-1), y1c = min(max(y1, 0), HH-1);
            int x0c = min(max(xx0,0), WW-1), x1c = min(max(xx1,0), WW-1);
            float w00 = (vy0 && vx0) ? (1.f-wy)*(1.f-wx) : 0.f;
            float w01 = (vy0 && vx1) ? (1.f-wy)*wx       : 0.f;
            float w10 = (vy1 && vx0) ? wy*(1.f-wx)       : 0.f;
            float w11 = (vy1 && vx1) ? wy*wx             : 0.f;
            int o00 = y0c*WW + x0c, o01 = y0c*WW + x1c;
            int o10 = y1c*WW + x0c, o11 = y1c*WW + x1c;

            const float* xg = xf + (size_t)g*8*HW;
            uint32_t hiw[4], low[4];
            #pragma unroll
            for (int c2 = 0; c2 < 4; c2++) {
                const float* xp0 = xg + (2*c2    )*HW;
                const float* xp1 = xg + (2*c2 + 1)*HW;
                float s0 = w00*__ldg(xp0 + o00) + w01*__ldg(xp0 + o01)
                         + w10*__ldg(xp0 + o10) + w11*__ldg(xp0 + o11);
                float s1 = w00*__ldg(xp1 + o00) + w01*__ldg(xp1 + o01)
                         + w10*__ldg(xp1 + o10) + w11*__ldg(xp1 + o11);
                uint32_t u0 = packhl(s0), u1 = packhl(s1);
                hiw[c2] = (u0 >> 16)      | (u1 & 0xFFFF0000u);
                low[c2] = (u0 & 0xFFFFu) | (u1 << 16);
            }
            *(uint4*)(AsH + m*DSA + sel*8) = make_uint4(hiw[0], hiw[1], hiw[2], hiw[3]);
            *(uint4*)(AsL + m*DSA + sel*8) = make_uint4(low[0], low[1], low[2], low[3]);
        }
        // ---- stage B: weights for chunk, [o][pair*8+c]
        {
            const uint32_t* src = wpk + ((size_t)(p0 + bpr)*64 + bo)*8 + bcq;
            uint32_t u0 = __ldg(src), u1 = __ldg(src+1), u2 = __ldg(src+2), u3 = __ldg(src+3);
            uint2 hv, lv;
            hv.x = (u0 >> 16) | (u1 & 0xFFFF0000u);
            hv.y = (u2 >> 16) | (u3 & 0xFFFF0000u);
            lv.x = (u0 & 0xFFFFu) | (u1 << 16);
            lv.y = (u2 & 0xFFFFu) | (u3 << 16);
            *(uint2*)(BsH + bo*DSA + bpr*8 + bcq) = hv;
            *(uint2*)(BsL + bo*DSA + bpr*8 + bcq) = lv;
        }
        __syncthreads();

        // ---- compute: 1 k16 x 4 n8 tiles x (hh, hl, lh)
        uint32_t aH[2][4], aL[2][4];
        #pragma unroll
        for (int mt = 0; mt < 2; mt++) {
            ldmx4(aH[mt], aHb + aOff[mt]);
            ldmx4(aL[mt], aLb + aOff[mt]);
        }
        #pragma unroll
        for (int j = 0; j < 4; j++) {
            uint32_t boff = (uint32_t)((wn*32 + j*8)*DSA*2) + bCom;
            uint32_t bH[2], bL[2];
            ldmx2(bH, bHb + boff);
            ldmx2(bL, bLb + boff);
            #pragma unroll
            for (int mt = 0; mt < 2; mt++) {
                mmabf(acc[mt][j], aH[mt], bH);
                mmabf(acc[mt][j], aH[mt], bL);
                mmabf(acc[mt][j], aL[mt], bH);
            }
        }
    }

    // ---- epilogue: transpose via smem -> coalesced px-major stores
    __syncthreads();
    {
        int r0 = lane >> 2, cp = (lane & 3) * 2;
        #pragma unroll
        for (int mt = 0; mt < 2; mt++) {
            #pragma unroll
            for (int j = 0; j < 4; j++) {
                int col = wn*32 + j*8 + cp;
                int row = wm*32 + mt*16 + r0;
                sOut[ col   *132 + row    ] = acc[mt][j][0];
                sOut[(col+1)*132 + row    ] = acc[mt][j][1];
                sOut[ col   *132 + row + 8] = acc[mt][j][2];
                sOut[(col+1)*132 + row + 8] = acc[mt][j][3];
            }
        }
    }
    __syncthreads();

    if (final_mode) {
        float* ob = out + ((size_t)(b*TT + frame)*CC)*HW + tileBase;
        #pragma unroll
        for (int it = 0; it < 32; it++) {
            int idx = it*256 + tid;
            int o = idx >> 7, pxl = idx & 127;
            ob[(size_t)o*HW + pxl] = sOut[o*132 + pxl];
        }
    } else {
        uint32_t* ob = g_z1p + (size_t)job*CC*HW + tileBase;
        #pragma unroll
        for (int it = 0; it < 32; it++) {
            int idx = it*256 + tid;
            int o = idx >> 7, pxl = idx & 127;
            ob[(size_t)o*HW + pxl] = packhl(sOut[o*132 + pxl]);
        }
    }
}

// ===========================================================================
extern "C" void kernel_launch(void* const* d_in, const int* in_sizes, int n_in,
                              void* d_out, int out_size) {
    const float* x        = (const float*)d_in[0];
    const float* w_off1   = (const float*)d_in[1];
    const float* b_off1   = (const float*)d_in[2];
    const float* w_off2   = (const float*)d_in[3];
    const float* b_off2   = (const float*)d_in[4];
    const float* w_align1 = (const float*)d_in[5];
    const float* w_alignf = (const float*)d_in[6];
    float* out = (float*)d_out;

    uint32_t *w5p = nullptr, *w3p = nullptr, *z1p = nullptr;
    uint32_t *x2p = nullptr, *xcp = nullptr, *wd1 = nullptr, *wdf = nullptr;
    cudaGetSymbolAddress((void**)&w5p, g_w5p);
    cudaGetSymbolAddress((void**)&w3p, g_w3p);
    cudaGetSymbolAddress((void**)&z1p, g_z1p);
    cudaGetSymbolAddress((void**)&x2p, g_x2p);
    cudaGetSymbolAddress((void**)&xcp, g_xcp);
    cudaGetSymbolAddress((void**)&wd1, g_wd1p);
    cudaGetSymbolAddress((void**)&wdf, g_wdfp);

    k_downsample<<<(BB*TT*CC*HW2 + 255)/256, 256>>>(x);
    k_center<<<(BB*CC*HW + 255)/256, 256>>>(x, out);
    k_wdeform<<<(72*64*8 + 255)/256, 256>>>(w_align1, w_alignf);
    k_pack<<<(OFFC*128*25 + 255)/256, 256>>>(w_off1, w5p, OFFC*128*25);
    k_pack<<<(OFFC*128*9  + 255)/256, 256>>>(w_off2, w3p, OFFC*128*9);
    k_tab<<<(128*25 + 255)/256, 256>>>();

    k_convMMA<false><<<dim3(HW2/128, NJ), 256>>>(x2p, x2p, w3p, b_off2);
    k_upsample2<<<(NJ*OFFC*HW2 + 255)/256, 256>>>();
    k_deformMMA<<<dim3(HW/128, NJ), 256>>>(x, out, wd1, 0);
    k_convMMA<true><<<dim3(HW/128, NJ), 256>>>(z1p, xcp, w5p, b_off1);
    k_deformMMA<<<dim3(HW/128, NJ), 256>>>(x, out, wdf, 1);
}